// round 1
// baseline (speedup 1.0000x reference)
#include <cuda_runtime.h>

#define NPIX 9216
#define HH 96
#define CC 21
#define CPAD 24
#define CRF_ITERS 5
#define APP_W 10.0f
#define SMO_W 3.0f
#define KSPLIT 16
#define JCHUNK (NPIX / KSPLIT)   // 576

// ---------------- persistent device scratch (no allocations allowed) ----------------
static __device__ float g_K[(size_t)NPIX * NPIX];   // bilateral kernel, APP_W folded in (340 MB)
static __device__ float g_feat[6 * NPIX];           // [sqnorm, f0..f4], struct-of-arrays
static __device__ float g_gauss[HH];                // 1-D smoothness taps exp(-d^2/18)
static __device__ float g_unary[CC * NPIX];         // logits, channel-major
static __device__ float g_out_pm[NPIX * CPAD];      // softmax probs, pixel-major, padded to 24
static __device__ float g_app[NPIX * CPAD];         // bilateral message (x APP_W), pixel-major
static __device__ float g_tmp[CC * NPIX];           // separable conv intermediate
static __device__ float g_smo[CC * NPIX];           // smoothness message, channel-major

// ---------------- packed f32x2 helpers ----------------
__device__ __forceinline__ unsigned long long pack2(float lo, float hi) {
    unsigned long long r;
    asm("mov.b64 %0, {%1, %2};" : "=l"(r) : "f"(lo), "f"(hi));
    return r;
}
__device__ __forceinline__ void unpack2(unsigned long long v, float &lo, float &hi) {
    asm("mov.b64 {%0, %1}, %2;" : "=f"(lo), "=f"(hi) : "l"(v));
}
__device__ __forceinline__ void fma2(unsigned long long &d, unsigned long long a, unsigned long long b) {
    asm("fma.rn.f32x2 %0, %1, %2, %3;" : "=l"(d) : "l"(a), "l"(b), "l"(d));
}

// ---------------- kernels ----------------

// Per-pixel bilateral features (already divided by sigmas) + squared norms + gauss taps.
__global__ void k_feat(const float* __restrict__ x) {
    int n = blockIdx.x * blockDim.x + threadIdx.x;
    if (n >= NPIX) return;
    int y = n / HH, xc = n % HH;
    float f0 = (float)y  * (1.0f / 30.0f);
    float f1 = (float)xc * (1.0f / 30.0f);
    float f2 = x[n]            * 10.0f;
    float f3 = x[NPIX + n]     * 10.0f;
    float f4 = x[2 * NPIX + n] * 10.0f;
    float sq = f0*f0 + f1*f1 + f2*f2 + f3*f3 + f4*f4;
    g_feat[n]            = sq;
    g_feat[NPIX     + n] = f0;
    g_feat[2*NPIX   + n] = f1;
    g_feat[3*NPIX   + n] = f2;
    g_feat[4*NPIX   + n] = f3;
    g_feat[5*NPIX   + n] = f4;
    if (n < HH) g_gauss[n] = expf(-(float)(n * n) * (1.0f / 18.0f));
}

// Build K[a][b] = APP_W * exp(-0.5 * max(||f_a - f_b||^2, 0)). Two elements per thread.
__global__ void k_build() {
    int a  = blockIdx.y;
    int bp = blockIdx.x * blockDim.x + threadIdx.x;   // 0..4607
    int b  = bp * 2;
    float sqa = g_feat[a];
    float a0 = g_feat[NPIX   + a];
    float a1 = g_feat[2*NPIX + a];
    float a2 = g_feat[3*NPIX + a];
    float a3 = g_feat[4*NPIX + a];
    float a4 = g_feat[5*NPIX + a];
    float2 sqb = *(const float2*)&g_feat[b];
    float2 b0  = *(const float2*)&g_feat[NPIX   + b];
    float2 b1  = *(const float2*)&g_feat[2*NPIX + b];
    float2 b2  = *(const float2*)&g_feat[3*NPIX + b];
    float2 b3  = *(const float2*)&g_feat[4*NPIX + b];
    float2 b4  = *(const float2*)&g_feat[5*NPIX + b];
    float dotx = a0*b0.x + a1*b1.x + a2*b2.x + a3*b3.x + a4*b4.x;
    float doty = a0*b0.y + a1*b1.y + a2*b2.y + a3*b3.y + a4*b4.y;
    float d2x = fmaxf(sqa + sqb.x - 2.0f * dotx, 0.0f);
    float d2y = fmaxf(sqa + sqb.y - 2.0f * doty, 0.0f);
    float2 kv;
    kv.x = APP_W * __expf(-0.5f * d2x);
    kv.y = APP_W * __expf(-0.5f * d2y);
    *(float2*)&g_K[(size_t)a * NPIX + b] = kv;
}

// unary = yhat; out = softmax(unary).
__global__ void k_init(const float* __restrict__ yhat, float* __restrict__ out_cm) {
    int n = blockIdx.x * blockDim.x + threadIdx.x;
    if (n >= NPIX) return;
    float u[CC];
    float mx = -1e30f;
    #pragma unroll
    for (int c = 0; c < CC; c++) {
        float v = yhat[c * NPIX + n];
        g_unary[c * NPIX + n] = v;
        u[c] = v;
        mx = fmaxf(mx, v);
    }
    float s = 0.0f;
    #pragma unroll
    for (int c = 0; c < CC; c++) { u[c] = __expf(u[c] - mx); s += u[c]; }
    float inv = 1.0f / s;
    #pragma unroll
    for (int c = 0; c < CC; c++) {
        float o = u[c] * inv;
        out_cm[c * NPIX + n] = o;
        g_out_pm[n * CPAD + c] = o;
    }
    g_out_pm[n * CPAD + 21] = 0.0f;
    g_out_pm[n * CPAD + 22] = 0.0f;
    g_out_pm[n * CPAD + 23] = 0.0f;
}

__global__ void k_zero() {
    int i = blockIdx.x * blockDim.x + threadIdx.x;
    if (i < NPIX * CPAD) g_app[i] = 0.0f;
}

// app[i][c] += sum_{j in chunk} K[j][i] * out[j][c]   (K symmetric -> coalesced along i).
// Each thread owns 2 rows x 24 channels in packed f32x2 accumulators. Split-K over grid.y.
__global__ void __launch_bounds__(128) k_gemm() {
    int t  = threadIdx.x;
    int i0 = blockIdx.x * 256 + 2 * t;
    int j0 = blockIdx.y * JCHUNK;
    int j1 = j0 + JCHUNK;

    unsigned long long acc[2][12];
    #pragma unroll
    for (int r = 0; r < 2; r++)
        #pragma unroll
        for (int p = 0; p < 12; p++) acc[r][p] = 0ull;

    const float* Kbase = g_K + i0;
    #pragma unroll 2
    for (int j = j0; j < j1; ++j) {
        float2 kv = __ldg((const float2*)(Kbase + (size_t)j * NPIX));
        unsigned long long ka = pack2(kv.x, kv.x);
        unsigned long long kb = pack2(kv.y, kv.y);
        const ulonglong2* bp = (const ulonglong2*)(g_out_pm + j * CPAD);
        #pragma unroll
        for (int p = 0; p < 6; p++) {
            ulonglong2 bv = __ldg(bp + p);
            fma2(acc[0][2*p],     ka, bv.x);
            fma2(acc[0][2*p + 1], ka, bv.y);
            fma2(acc[1][2*p],     kb, bv.x);
            fma2(acc[1][2*p + 1], kb, bv.y);
        }
    }

    #pragma unroll
    for (int r = 0; r < 2; r++) {
        #pragma unroll
        for (int p = 0; p < 12; p++) {
            float lo, hi;
            unpack2(acc[r][p], lo, hi);
            atomicAdd(&g_app[(i0 + r) * CPAD + 2 * p],     lo);
            atomicAdd(&g_app[(i0 + r) * CPAD + 2 * p + 1], hi);
        }
    }
}

// Separable smoothness: horizontal pass.
__global__ void k_convx(const float* __restrict__ out_cm) {
    __shared__ float sg[HH];
    if (threadIdx.x < HH) sg[threadIdx.x] = g_gauss[threadIdx.x];
    __syncthreads();
    int idx = blockIdx.x * blockDim.x + threadIdx.x;
    if (idx >= CC * NPIX) return;
    int xp = idx % HH;
    const float* row = out_cm + (idx - xp);
    float s = 0.0f;
    #pragma unroll 8
    for (int xx = 0; xx < HH; ++xx) {
        int d = xx - xp; d = (d < 0) ? -d : d;
        s += row[xx] * sg[d];
    }
    g_tmp[idx] = s;
}

// Separable smoothness: vertical pass.
__global__ void k_convy() {
    __shared__ float sg[HH];
    if (threadIdx.x < HH) sg[threadIdx.x] = g_gauss[threadIdx.x];
    __syncthreads();
    int idx = blockIdx.x * blockDim.x + threadIdx.x;
    if (idx >= CC * NPIX) return;
    int xp = idx % HH;
    int yp = (idx / HH) % HH;
    int c  = idx / NPIX;
    const float* col = g_tmp + c * NPIX + xp;
    float s = 0.0f;
    #pragma unroll 8
    for (int y = 0; y < HH; ++y) {
        int d = y - yp; d = (d < 0) ? -d : d;
        s += col[y * HH] * sg[d];
    }
    g_smo[idx] = s;
}

// msg = app + SMO_W*smo; pw = mu^T msg; unary += pw; out = softmax(unary).
__global__ void k_combine(const float* __restrict__ mu, float* __restrict__ out_cm) {
    __shared__ float smu[CC * CC];
    for (int i = threadIdx.x; i < CC * CC; i += blockDim.x) smu[i] = mu[i];
    __syncthreads();
    int n = blockIdx.x * blockDim.x + threadIdx.x;
    if (n >= NPIX) return;
    float m[CC];
    #pragma unroll
    for (int c = 0; c < CC; c++)
        m[c] = g_app[n * CPAD + c] + SMO_W * g_smo[c * NPIX + n];
    float u[CC];
    float mx = -1e30f;
    #pragma unroll
    for (int c = 0; c < CC; c++) {
        float s = 0.0f;
        #pragma unroll
        for (int c2 = 0; c2 < CC; c2++) s = fmaf(smu[c2 * CC + c], m[c2], s);
        float v = g_unary[c * NPIX + n] + s;
        g_unary[c * NPIX + n] = v;
        u[c] = v;
        mx = fmaxf(mx, v);
    }
    float s = 0.0f;
    #pragma unroll
    for (int c = 0; c < CC; c++) { u[c] = __expf(u[c] - mx); s += u[c]; }
    float inv = 1.0f / s;
    #pragma unroll
    for (int c = 0; c < CC; c++) {
        float o = u[c] * inv;
        out_cm[c * NPIX + n] = o;
        g_out_pm[n * CPAD + c] = o;
    }
    g_out_pm[n * CPAD + 21] = 0.0f;
    g_out_pm[n * CPAD + 22] = 0.0f;
    g_out_pm[n * CPAD + 23] = 0.0f;
}

// ---------------- launch ----------------
extern "C" void kernel_launch(void* const* d_in, const int* in_sizes, int n_in,
                              void* d_out, int out_size) {
    const float* x    = (const float*)d_in[0];
    const float* yhat = (const float*)d_in[1];
    const float* mu   = (const float*)d_in[2];
    float* out = (float*)d_out;

    k_feat<<<(NPIX + 255) / 256, 256>>>(x);
    k_build<<<dim3(18, NPIX), 256>>>();
    k_init<<<(NPIX + 255) / 256, 256>>>(yhat, out);

    for (int it = 0; it < CRF_ITERS; ++it) {
        k_zero<<<(NPIX * CPAD + 255) / 256, 256>>>();
        k_gemm<<<dim3(36, KSPLIT), 128>>>();
        k_convx<<<(CC * NPIX + 127) / 128, 128>>>(out);
        k_convy<<<(CC * NPIX + 127) / 128, 128>>>();
        k_combine<<<(NPIX + 127) / 128, 128>>>(mu, out);
    }
}

// round 3
// speedup vs baseline: 1.9516x; 1.9516x over previous
#include <cuda_runtime.h>
#include <cuda_fp16.h>
#include <cstdint>

#define NPIX 9216
#define HH 96
#define CC 21
#define NB 24            // padded class dim (3 x n8 MMA tiles)
#define CRF_ITERS 5
#define APP_W 10.0f
#define SMO_W 3.0f

#define MT 64            // M tile per CTA
#define KT 128           // K tile
#define NT (NPIX / KT)   // 72 k-tiles
#define NCTA (NPIX / MT) // 144 CTAs

// SMEM tile layout (bytes). Row pitch 136 halves = 272 B (16B-phase shift per row
// -> ldmatrix conflict-free without swizzle).
#define SKP 136
#define ROWB 272
#define AHI 0
#define ALO (64 * ROWB)            // 17408
#define BHI (2 * 64 * ROWB)        // 34816
#define BLO (BHI + NB * ROWB)      // 41344
#define STAGEB (BLO + NB * ROWB)   // 47872
#define NSTAGE 4
#define FULLB (128 * 256 + 2 * NB * 256)   // 45056 expected tx bytes per stage
#define GEMM_SMEM (NSTAGE * STAGEB)        // 191488

// ---------------- persistent device scratch ----------------
static __device__ __half g_Khi[(size_t)NPIX * NPIX];   // 170 MB
static __device__ __half g_Klo[(size_t)NPIX * NPIX];   // 170 MB
static __device__ float  g_feat[6 * NPIX];
static __device__ float  g_gauss[HH];
static __device__ float  g_unary[CC * NPIX];
static __device__ __half g_Bhi[NB * NPIX];             // class-major fp16 probs (hi)
static __device__ __half g_Blo[NB * NPIX];             // residual (lo)
static __device__ float  g_app[(size_t)NPIX * NB];     // bilateral message
static __device__ float  g_tmp[CC * NPIX];
static __device__ float  g_smo[CC * NPIX];

// ---------------- PTX helpers (compute_100-safe: no tcgen05) ----------------
__device__ __forceinline__ uint32_t smem_u32(const void* p) {
    uint32_t a;
    asm("{ .reg .u64 t; cvta.to.shared.u64 t, %1; cvt.u32.u64 %0, t; }" : "=r"(a) : "l"(p));
    return a;
}
__device__ __forceinline__ void mbar_init(uint32_t a, uint32_t c) {
    asm volatile("mbarrier.init.shared.b64 [%0], %1;" :: "r"(a), "r"(c) : "memory");
}
__device__ __forceinline__ void mbar_expect_tx(uint32_t a, uint32_t bytes) {
    asm volatile("mbarrier.arrive.expect_tx.shared.b64 _, [%0], %1;" :: "r"(a), "r"(bytes) : "memory");
}
__device__ __forceinline__ void mbar_wait(uint32_t mbar, uint32_t parity) {
    asm volatile(
        "{\n\t.reg .pred P1;\n\t"
        "WL%=:\n\t"
        "mbarrier.try_wait.parity.shared.b64 P1, [%0], %1;\n\t"
        "@!P1 bra WL%=;\n\t}"
        :: "r"(mbar), "r"(parity) : "memory");
}
__device__ __forceinline__ void bulk_cp(uint32_t dst, const void* src, uint32_t bytes, uint32_t mbar) {
    asm volatile(
        "cp.async.bulk.shared::cluster.global.mbarrier::complete_tx::bytes [%0], [%1], %2, [%3];"
        :: "r"(dst), "l"(src), "r"(bytes), "r"(mbar) : "memory");
}
__device__ __forceinline__ void ldsm4(uint32_t& r0, uint32_t& r1, uint32_t& r2, uint32_t& r3, uint32_t addr) {
    asm volatile("ldmatrix.sync.aligned.m8n8.x4.shared.b16 {%0,%1,%2,%3}, [%4];"
        : "=r"(r0), "=r"(r1), "=r"(r2), "=r"(r3) : "r"(addr));
}
__device__ __forceinline__ void ldsm2(uint32_t& r0, uint32_t& r1, uint32_t addr) {
    asm volatile("ldmatrix.sync.aligned.m8n8.x2.shared.b16 {%0,%1}, [%2];"
        : "=r"(r0), "=r"(r1) : "r"(addr));
}
__device__ __forceinline__ void hmma(float* c, const uint32_t* a, const uint32_t* b) {
    asm volatile(
        "mma.sync.aligned.m16n8k16.row.col.f32.f16.f16.f32 "
        "{%0,%1,%2,%3}, {%4,%5,%6,%7}, {%8,%9}, {%0,%1,%2,%3};"
        : "+f"(c[0]), "+f"(c[1]), "+f"(c[2]), "+f"(c[3])
        : "r"(a[0]), "r"(a[1]), "r"(a[2]), "r"(a[3]), "r"(b[0]), "r"(b[1]));
}

// ---------------- kernels ----------------

__global__ void k_feat(const float* __restrict__ x) {
    int n = blockIdx.x * blockDim.x + threadIdx.x;
    if (n >= NPIX) return;
    int y = n / HH, xc = n % HH;
    float f0 = (float)y  * (1.0f / 30.0f);
    float f1 = (float)xc * (1.0f / 30.0f);
    float f2 = x[n]            * 10.0f;
    float f3 = x[NPIX + n]     * 10.0f;
    float f4 = x[2 * NPIX + n] * 10.0f;
    float sq = f0*f0 + f1*f1 + f2*f2 + f3*f3 + f4*f4;
    g_feat[n]            = sq;
    g_feat[NPIX     + n] = f0;
    g_feat[2*NPIX   + n] = f1;
    g_feat[3*NPIX   + n] = f2;
    g_feat[4*NPIX   + n] = f3;
    g_feat[5*NPIX   + n] = f4;
    if (n < HH) g_gauss[n] = expf(-(float)(n * n) * (1.0f / 18.0f));
}

// K[a][b] = APP_W * exp(-0.5*||fa-fb||^2), stored as fp16 hi + fp16 residual.
__global__ void k_build() {
    int a  = blockIdx.y;
    int b  = (blockIdx.x * blockDim.x + threadIdx.x) * 2;
    float sqa = g_feat[a];
    float a0 = g_feat[NPIX   + a];
    float a1 = g_feat[2*NPIX + a];
    float a2 = g_feat[3*NPIX + a];
    float a3 = g_feat[4*NPIX + a];
    float a4 = g_feat[5*NPIX + a];
    float2 sqb = *(const float2*)&g_feat[b];
    float2 b0  = *(const float2*)&g_feat[NPIX   + b];
    float2 b1  = *(const float2*)&g_feat[2*NPIX + b];
    float2 b2  = *(const float2*)&g_feat[3*NPIX + b];
    float2 b3  = *(const float2*)&g_feat[4*NPIX + b];
    float2 b4  = *(const float2*)&g_feat[5*NPIX + b];
    float dotx = a0*b0.x + a1*b1.x + a2*b2.x + a3*b3.x + a4*b4.x;
    float doty = a0*b0.y + a1*b1.y + a2*b2.y + a3*b3.y + a4*b4.y;
    float kx = APP_W * __expf(-0.5f * fmaxf(sqa + sqb.x - 2.0f * dotx, 0.0f));
    float ky = APP_W * __expf(-0.5f * fmaxf(sqa + sqb.y - 2.0f * doty, 0.0f));
    __half hx = __float2half_rn(kx);
    __half hy = __float2half_rn(ky);
    __half lx = __float2half_rn(kx - __half2float(hx));
    __half ly = __float2half_rn(ky - __half2float(hy));
    size_t idx = (size_t)a * NPIX + b;
    *(__half2*)&g_Khi[idx] = __halves2half2(hx, hy);
    *(__half2*)&g_Klo[idx] = __halves2half2(lx, ly);
}

__device__ __forceinline__ void write_probs(int n, const float* u, float inv, float* out_cm) {
    #pragma unroll
    for (int c = 0; c < CC; c++) {
        float o = u[c] * inv;
        out_cm[c * NPIX + n] = o;
        __half h = __float2half_rn(o);
        g_Bhi[c * NPIX + n] = h;
        g_Blo[c * NPIX + n] = __float2half_rn(o - __half2float(h));
    }
}

__global__ void k_init(const float* __restrict__ yhat, float* __restrict__ out_cm) {
    int n = blockIdx.x * blockDim.x + threadIdx.x;
    if (n >= NPIX) return;
    float u[CC];
    float mx = -1e30f;
    #pragma unroll
    for (int c = 0; c < CC; c++) {
        float v = yhat[c * NPIX + n];
        g_unary[c * NPIX + n] = v;
        u[c] = v;
        mx = fmaxf(mx, v);
    }
    float s = 0.0f;
    #pragma unroll
    for (int c = 0; c < CC; c++) { u[c] = __expf(u[c] - mx); s += u[c]; }
    write_probs(n, u, 1.0f / s, out_cm);
    #pragma unroll
    for (int c = CC; c < NB; c++) {          // padded rows stay zero all run
        g_Bhi[c * NPIX + n] = __float2half_rn(0.0f);
        g_Blo[c * NPIX + n] = __float2half_rn(0.0f);
    }
}

// Issue bulk copies for one stage: A hi/lo 64x128 halves + B hi/lo 24x128 halves.
__device__ __forceinline__ void fill_stage(uint32_t st, int m0, int t, uint32_t mb, int tid) {
    int k0 = t * KT;
    if (tid < 64) {
        const __half* sh = g_Khi + (size_t)(m0 + tid) * NPIX + k0;
        const __half* sl = g_Klo + (size_t)(m0 + tid) * NPIX + k0;
        bulk_cp(st + AHI + tid * ROWB, sh, 256, mb);
        bulk_cp(st + ALO + tid * ROWB, sl, 256, mb);
    } else if (tid < 64 + 2 * NB) {
        int i = tid - 64;
        int pl = i / NB, n = i % NB;
        const __half* s = (pl ? g_Blo : g_Bhi) + (size_t)n * NPIX + k0;
        bulk_cp(st + (pl ? BLO : BHI) + n * ROWB, s, 256, mb);
    }
}

__global__ void __launch_bounds__(128, 1) k_gemm_mma() {
    extern __shared__ char smem[];
    __shared__ uint64_t mbar_s[NSTAGE];
    uint32_t sb = smem_u32(smem);
    int tid = threadIdx.x;
    int lane = tid & 31;
    int w = tid >> 5;
    int m0 = blockIdx.x * MT;

    uint32_t mb[NSTAGE];
    #pragma unroll
    for (int s = 0; s < NSTAGE; s++) mb[s] = smem_u32(&mbar_s[s]);

    if (tid < NSTAGE) mbar_init(mb[tid], 1);
    __syncthreads();
    if (tid == 0) {
        #pragma unroll
        for (int s = 0; s < NSTAGE; s++) mbar_expect_tx(mb[s], FULLB);
    }
    __syncthreads();
    #pragma unroll
    for (int s = 0; s < NSTAGE; s++)
        fill_stage(sb + s * STAGEB, m0, s, mb[s], tid);

    // per-thread ldmatrix offsets
    uint32_t a_off = ((uint32_t)((w * 16 + (lane & 15)) * SKP + (lane >> 4) * 8)) * 2;
    int l2 = lane & 15;
    uint32_t b_off = ((uint32_t)((l2 & 7) * SKP + ((l2 >> 3) & 1) * 8)) * 2;

    float acc[3][4];
    #pragma unroll
    for (int nt = 0; nt < 3; nt++)
        #pragma unroll
        for (int q = 0; q < 4; q++) acc[nt][q] = 0.0f;

    for (int t = 0; t < NT; ++t) {
        int s = t & (NSTAGE - 1);
        uint32_t st = sb + s * STAGEB;
        mbar_wait(mb[s], (t >> 2) & 1);

        #pragma unroll
        for (int ks = 0; ks < 8; ++ks) {
            uint32_t ah[4], al[4];
            ldsm4(ah[0], ah[1], ah[2], ah[3], st + AHI + a_off + ks * 32);
            ldsm4(al[0], al[1], al[2], al[3], st + ALO + a_off + ks * 32);
            #pragma unroll
            for (int nt = 0; nt < 3; ++nt) {
                uint32_t bh[2], bl[2];
                ldsm2(bh[0], bh[1], st + BHI + nt * 8 * ROWB + b_off + ks * 32);
                ldsm2(bl[0], bl[1], st + BLO + nt * 8 * ROWB + b_off + ks * 32);
                hmma(acc[nt], ah, bh);
                hmma(acc[nt], ah, bl);
                hmma(acc[nt], al, bh);
            }
        }
        __syncthreads();                 // everyone done reading stage s
        if (t + NSTAGE < NT) {
            if (tid == 0) mbar_expect_tx(mb[s], FULLB);
            __syncthreads();             // expect_tx before any complete_tx
            fill_stage(st, m0, t + NSTAGE, mb[s], tid);
        }
    }

    // epilogue: C fragment -> g_app (row-major, stride NB)
    int r0 = m0 + w * 16 + (lane >> 2);
    int cb = (lane & 3) * 2;
    #pragma unroll
    for (int nt = 0; nt < 3; ++nt) {
        *(float2*)&g_app[(size_t)r0 * NB + nt * 8 + cb]       = make_float2(acc[nt][0], acc[nt][1]);
        *(float2*)&g_app[(size_t)(r0 + 8) * NB + nt * 8 + cb] = make_float2(acc[nt][2], acc[nt][3]);
    }
}

// Separable smoothness: horizontal pass.
__global__ void k_convx(const float* __restrict__ out_cm) {
    __shared__ float sg[HH];
    if (threadIdx.x < HH) sg[threadIdx.x] = g_gauss[threadIdx.x];
    __syncthreads();
    int idx = blockIdx.x * blockDim.x + threadIdx.x;
    if (idx >= CC * NPIX) return;
    int xp = idx % HH;
    const float* row = out_cm + (idx - xp);
    float s = 0.0f;
    #pragma unroll 8
    for (int xx = 0; xx < HH; ++xx) {
        int d = xx - xp; d = (d < 0) ? -d : d;
        s += row[xx] * sg[d];
    }
    g_tmp[idx] = s;
}

// Separable smoothness: vertical pass.
__global__ void k_convy() {
    __shared__ float sg[HH];
    if (threadIdx.x < HH) sg[threadIdx.x] = g_gauss[threadIdx.x];
    __syncthreads();
    int idx = blockIdx.x * blockDim.x + threadIdx.x;
    if (idx >= CC * NPIX) return;
    int xp = idx % HH;
    int yp = (idx / HH) % HH;
    int c  = idx / NPIX;
    const float* col = g_tmp + c * NPIX + xp;
    float s = 0.0f;
    #pragma unroll 8
    for (int y = 0; y < HH; ++y) {
        int d = y - yp; d = (d < 0) ? -d : d;
        s += col[y * HH] * sg[d];
    }
    g_smo[idx] = s;
}

__global__ void k_combine(const float* __restrict__ mu, float* __restrict__ out_cm) {
    __shared__ float smu[CC * CC];
    for (int i = threadIdx.x; i < CC * CC; i += blockDim.x) smu[i] = mu[i];
    __syncthreads();
    int n = blockIdx.x * blockDim.x + threadIdx.x;
    if (n >= NPIX) return;
    float m[CC];
    #pragma unroll
    for (int c = 0; c < CC; c++)
        m[c] = g_app[(size_t)n * NB + c] + SMO_W * g_smo[c * NPIX + n];
    float u[CC];
    float mx = -1e30f;
    #pragma unroll
    for (int c = 0; c < CC; c++) {
        float s = 0.0f;
        #pragma unroll
        for (int c2 = 0; c2 < CC; c2++) s = fmaf(smu[c2 * CC + c], m[c2], s);
        float v = g_unary[c * NPIX + n] + s;
        g_unary[c * NPIX + n] = v;
        u[c] = v;
        mx = fmaxf(mx, v);
    }
    float s = 0.0f;
    #pragma unroll
    for (int c = 0; c < CC; c++) { u[c] = __expf(u[c] - mx); s += u[c]; }
    write_probs(n, u, 1.0f / s, out_cm);
}

// ---------------- launch ----------------
extern "C" void kernel_launch(void* const* d_in, const int* in_sizes, int n_in,
                              void* d_out, int out_size) {
    const float* x    = (const float*)d_in[0];
    const float* yhat = (const float*)d_in[1];
    const float* mu   = (const float*)d_in[2];
    float* out = (float*)d_out;

    cudaFuncSetAttribute(k_gemm_mma, cudaFuncAttributeMaxDynamicSharedMemorySize, GEMM_SMEM);

    k_feat<<<(NPIX + 255) / 256, 256>>>(x);
    k_build<<<dim3(18, NPIX), 256>>>();
    k_init<<<(NPIX + 255) / 256, 256>>>(yhat, out);

    for (int it = 0; it < CRF_ITERS; ++it) {
        k_gemm_mma<<<NCTA, 128, GEMM_SMEM>>>();
        k_convx<<<(CC * NPIX + 127) / 128, 128>>>(out);
        k_convy<<<(CC * NPIX + 127) / 128, 128>>>();
        k_combine<<<(NPIX + 127) / 128, 128>>>(mu, out);
    }
}

// round 4
// speedup vs baseline: 2.6463x; 1.3559x over previous
#include <cuda_runtime.h>
#include <cuda_fp16.h>
#include <cstdint>

#define NPIX 9216
#define HH 96
#define CC 21
#define NB 24
#define CRF_ITERS 5
#define APP_W 10.0f
#define SMO_W 3.0f

#define PB 72                       // 128-row blocks
#define NPAIR (PB * (PB + 1) / 2)   // 2628 pair-blocks
#define SKP 136                     // smem row pitch in halves
#define ROWB 272                    // bytes

// GEMM stage smem layout (bytes)
#define AHI2 0
#define ALO2 34816
#define PJHI 69632
#define PJLO 76160
#define PIHI 82688
#define PILO 89216
#define GEMM_SMEM 95744
#define FULLB 90112                 // expected tx bytes

// ---------------- persistent device scratch ----------------
static __device__ __half g_Khi[(size_t)NPIX * NPIX];
static __device__ __half g_Klo[(size_t)NPIX * NPIX];
static __device__ float  g_feat[6 * NPIX];
static __device__ float  g_gauss[HH];
static __device__ float  g_unary[CC * NPIX];
static __device__ __half g_Bhi[NB * NPIX];
static __device__ __half g_Blo[NB * NPIX];
static __device__ float  g_app[(size_t)NPIX * NB];
static __device__ float  g_tmp[CC * NPIX];
static __device__ float  g_smo[CC * NPIX];

// ---------------- PTX helpers ----------------
__device__ __forceinline__ uint32_t smem_u32(const void* p) {
    uint32_t a;
    asm("{ .reg .u64 t; cvta.to.shared.u64 t, %1; cvt.u32.u64 %0, t; }" : "=r"(a) : "l"(p));
    return a;
}
__device__ __forceinline__ void mbar_init(uint32_t a, uint32_t c) {
    asm volatile("mbarrier.init.shared.b64 [%0], %1;" :: "r"(a), "r"(c) : "memory");
}
__device__ __forceinline__ void mbar_expect_tx(uint32_t a, uint32_t bytes) {
    asm volatile("mbarrier.arrive.expect_tx.shared.b64 _, [%0], %1;" :: "r"(a), "r"(bytes) : "memory");
}
__device__ __forceinline__ void mbar_wait(uint32_t mbar, uint32_t parity) {
    asm volatile(
        "{\n\t.reg .pred P1;\n\t"
        "WL%=:\n\t"
        "mbarrier.try_wait.parity.shared.b64 P1, [%0], %1;\n\t"
        "@!P1 bra WL%=;\n\t}"
        :: "r"(mbar), "r"(parity) : "memory");
}
__device__ __forceinline__ void bulk_cp(uint32_t dst, const void* src, uint32_t bytes, uint32_t mbar) {
    asm volatile(
        "cp.async.bulk.shared::cluster.global.mbarrier::complete_tx::bytes [%0], [%1], %2, [%3];"
        :: "r"(dst), "l"(src), "r"(bytes), "r"(mbar) : "memory");
}
__device__ __forceinline__ void ldsm4(uint32_t& r0, uint32_t& r1, uint32_t& r2, uint32_t& r3, uint32_t addr) {
    asm volatile("ldmatrix.sync.aligned.m8n8.x4.shared.b16 {%0,%1,%2,%3}, [%4];"
        : "=r"(r0), "=r"(r1), "=r"(r2), "=r"(r3) : "r"(addr));
}
__device__ __forceinline__ void ldsm4t(uint32_t& r0, uint32_t& r1, uint32_t& r2, uint32_t& r3, uint32_t addr) {
    asm volatile("ldmatrix.sync.aligned.m8n8.x4.trans.shared.b16 {%0,%1,%2,%3}, [%4];"
        : "=r"(r0), "=r"(r1), "=r"(r2), "=r"(r3) : "r"(addr));
}
__device__ __forceinline__ void ldsm2(uint32_t& r0, uint32_t& r1, uint32_t addr) {
    asm volatile("ldmatrix.sync.aligned.m8n8.x2.shared.b16 {%0,%1}, [%2];"
        : "=r"(r0), "=r"(r1) : "r"(addr));
}
__device__ __forceinline__ void hmma(float* c, const uint32_t* a, const uint32_t* b) {
    asm volatile(
        "mma.sync.aligned.m16n8k16.row.col.f32.f16.f16.f32 "
        "{%0,%1,%2,%3}, {%4,%5,%6,%7}, {%8,%9}, {%0,%1,%2,%3};"
        : "+f"(c[0]), "+f"(c[1]), "+f"(c[2]), "+f"(c[3])
        : "r"(a[0]), "r"(a[1]), "r"(a[2]), "r"(a[3]), "r"(b[0]), "r"(b[1]));
}

// triangular decode: bid -> (col, row) with col <= row, row*(row+1)/2 + col = bid
__device__ __forceinline__ void tri_decode(int bid, int& lo, int& hi) {
    int r = (int)((sqrtf(8.0f * (float)bid + 1.0f) - 1.0f) * 0.5f);
    while ((r + 1) * (r + 2) / 2 <= bid) ++r;
    while (r * (r + 1) / 2 > bid) --r;
    hi = r;
    lo = bid - r * (r + 1) / 2;
}

// ---------------- kernels ----------------

__global__ void k_feat(const float* __restrict__ x) {
    int n = blockIdx.x * blockDim.x + threadIdx.x;
    if (n >= NPIX) return;
    int y = n / HH, xc = n % HH;
    float f0 = (float)y  * (1.0f / 30.0f);
    float f1 = (float)xc * (1.0f / 30.0f);
    float f2 = x[n]            * 10.0f;
    float f3 = x[NPIX + n]     * 10.0f;
    float f4 = x[2 * NPIX + n] * 10.0f;
    float sq = f0*f0 + f1*f1 + f2*f2 + f3*f3 + f4*f4;
    g_feat[n]            = sq;
    g_feat[NPIX     + n] = f0;
    g_feat[2*NPIX   + n] = f1;
    g_feat[3*NPIX   + n] = f2;
    g_feat[4*NPIX   + n] = f3;
    g_feat[5*NPIX   + n] = f4;
    if (n < HH) g_gauss[n] = expf(-(float)(n * n) * (1.0f / 18.0f));
}

// Symmetric build: upper-tri 64x64 tiles; direct write + smem-transposed mirror write.
#define BTB 144   // 64-row blocks
__global__ void __launch_bounds__(256) k_build_sym() {
    __shared__ __half sHI[64][72];
    __shared__ __half sLO[64][72];
    int ta, tb;
    tri_decode(blockIdx.x, ta, tb);   // ta <= tb
    int tid = threadIdx.x;
    int r  = tid >> 2;                // row within a-block
    int bq = (tid & 3) * 16;          // b-chunk start

    int a = ta * 64 + r;
    float sqa = g_feat[a];
    float a0 = g_feat[NPIX   + a];
    float a1 = g_feat[2*NPIX + a];
    float a2 = g_feat[3*NPIX + a];
    float a3 = g_feat[4*NPIX + a];
    float a4 = g_feat[5*NPIX + a];

    #pragma unroll
    for (int q = 0; q < 8; ++q) {
        int b = tb * 64 + bq + 2 * q;
        float2 sqb = *(const float2*)&g_feat[b];
        float2 b0  = *(const float2*)&g_feat[NPIX   + b];
        float2 b1  = *(const float2*)&g_feat[2*NPIX + b];
        float2 b2  = *(const float2*)&g_feat[3*NPIX + b];
        float2 b3  = *(const float2*)&g_feat[4*NPIX + b];
        float2 b4  = *(const float2*)&g_feat[5*NPIX + b];
        float dotx = a0*b0.x + a1*b1.x + a2*b2.x + a3*b3.x + a4*b4.x;
        float doty = a0*b0.y + a1*b1.y + a2*b2.y + a3*b3.y + a4*b4.y;
        float kx = APP_W * __expf(-0.5f * fmaxf(sqa + sqb.x - 2.0f * dotx, 0.0f));
        float ky = APP_W * __expf(-0.5f * fmaxf(sqa + sqb.y - 2.0f * doty, 0.0f));
        __half hx = __float2half_rn(kx);
        __half hy = __float2half_rn(ky);
        __half lx = __float2half_rn(kx - __half2float(hx));
        __half ly = __float2half_rn(ky - __half2float(hy));
        size_t idx = (size_t)a * NPIX + b;
        *(__half2*)&g_Khi[idx] = __halves2half2(hx, hy);
        *(__half2*)&g_Klo[idx] = __halves2half2(lx, ly);
        int bb = bq + 2 * q;
        sHI[r][bb] = hx; sHI[r][bb + 1] = hy;
        sLO[r][bb] = lx; sLO[r][bb + 1] = ly;
    }
    __syncthreads();

    // mirror write: row rb of tb-block, 16 a-cols starting aq
    int rb = tid >> 2;
    int aq = (tid & 3) * 16;
    int bg = tb * 64 + rb;
    size_t base = (size_t)bg * NPIX + ta * 64 + aq;
    #pragma unroll
    for (int q = 0; q < 8; ++q) {
        __half2 h = __halves2half2(sHI[aq + 2*q][rb], sHI[aq + 2*q + 1][rb]);
        __half2 l = __halves2half2(sLO[aq + 2*q][rb], sLO[aq + 2*q + 1][rb]);
        *(__half2*)&g_Khi[base + 2*q] = h;
        *(__half2*)&g_Klo[base + 2*q] = l;
    }
}

__device__ __forceinline__ void write_probs(int n, const float* u, float inv, float* out_cm) {
    #pragma unroll
    for (int c = 0; c < CC; c++) {
        float o = u[c] * inv;
        out_cm[c * NPIX + n] = o;
        __half h = __float2half_rn(o);
        g_Bhi[c * NPIX + n] = h;
        g_Blo[c * NPIX + n] = __float2half_rn(o - __half2float(h));
    }
}

__global__ void k_init(const float* __restrict__ yhat, float* __restrict__ out_cm) {
    int n = blockIdx.x * blockDim.x + threadIdx.x;
    if (n >= NPIX) return;
    float u[CC];
    float mx = -1e30f;
    #pragma unroll
    for (int c = 0; c < CC; c++) {
        float v = yhat[c * NPIX + n];
        g_unary[c * NPIX + n] = v;
        u[c] = v;
        mx = fmaxf(mx, v);
    }
    float s = 0.0f;
    #pragma unroll
    for (int c = 0; c < CC; c++) { u[c] = __expf(u[c] - mx); s += u[c]; }
    write_probs(n, u, 1.0f / s, out_cm);
    #pragma unroll
    for (int c = CC; c < NB; c++) {
        g_Bhi[c * NPIX + n] = __float2half_rn(0.0f);
        g_Blo[c * NPIX + n] = __float2half_rn(0.0f);
    }
}

__global__ void k_zero() {
    int i = blockIdx.x * blockDim.x + threadIdx.x;
    if (i < NPIX * NB) g_app[i] = 0.0f;
}

// Symmetric pair-block GEMM: CTA (I,J), I<=J.
//   out_I += K_IJ @ P_J   (straight)
//   out_J += K_IJ^T @ P_I (transposed, skipped when I==J)
__global__ void __launch_bounds__(256, 2) k_gemm_sym() {
    extern __shared__ char smem[];
    __shared__ uint64_t mbar_s;
    uint32_t sb = smem_u32(smem);
    uint32_t mb = smem_u32(&mbar_s);
    int tid = threadIdx.x;
    int lane = tid & 31;
    int w = tid >> 5;

    int I, J;
    tri_decode(blockIdx.x, I, J);

    if (tid == 0) mbar_init(mb, 1);
    __syncthreads();
    if (tid == 0) mbar_expect_tx(mb, FULLB);
    __syncthreads();

    // fill: A rows (128 x 2 planes), P_J (24 x 2), P_I (24 x 2)
    if (tid < 128) {
        size_t src = (size_t)(I * 128 + tid) * NPIX + J * 128;
        bulk_cp(sb + AHI2 + tid * ROWB, g_Khi + src, 256, mb);
        bulk_cp(sb + ALO2 + tid * ROWB, g_Klo + src, 256, mb);
    } else if (tid < 224) {
        int i = tid - 128;
        int grp = i / NB;           // 0:PJhi 1:PJlo 2:PIhi 3:PIlo
        int c = i % NB;
        const __half* srcp = (grp & 1) ? g_Blo : g_Bhi;
        int blk = (grp < 2) ? J : I;
        uint32_t dst = sb + ((grp == 0) ? PJHI : (grp == 1) ? PJLO : (grp == 2) ? PIHI : PILO) + c * ROWB;
        bulk_cp(dst, srcp + (size_t)c * NPIX + blk * 128, 256, mb);
    }

    // frag address offsets
    uint32_t a_off = (uint32_t)((w * 16 + (lane & 15)) * ROWB + (lane >> 4) * 16);
    int gg = lane >> 3;
    uint32_t t_row = (uint32_t)((gg >> 1) * 8 + (lane & 7));        // + ks*16
    uint32_t t_off = t_row * ROWB + (uint32_t)(w * 16 + (gg & 1) * 8) * 2;
    int l2 = lane & 15;
    uint32_t b_off = (uint32_t)((l2 & 7) * ROWB + ((l2 >> 3) & 1) * 16);

    float acc[3][3][4];   // [term hh/hl/lh][nt][4]
    #pragma unroll
    for (int tm = 0; tm < 3; tm++)
        #pragma unroll
        for (int nt = 0; nt < 3; nt++)
            #pragma unroll
            for (int q = 0; q < 4; q++) acc[tm][nt][q] = 0.0f;

    mbar_wait(mb, 0);

    // ---- straight product: out_I rows w*16.., k over J-block ----
    #pragma unroll
    for (int ks = 0; ks < 8; ++ks) {
        uint32_t ah[4], al[4];
        ldsm4(ah[0], ah[1], ah[2], ah[3], sb + AHI2 + a_off + ks * 32);
        ldsm4(al[0], al[1], al[2], al[3], sb + ALO2 + a_off + ks * 32);
        #pragma unroll
        for (int nt = 0; nt < 3; ++nt) {
            uint32_t bh[2], bl[2];
            ldsm2(bh[0], bh[1], sb + PJHI + nt * 8 * ROWB + b_off + ks * 32);
            ldsm2(bl[0], bl[1], sb + PJLO + nt * 8 * ROWB + b_off + ks * 32);
            hmma(acc[0][nt], ah, bh);
            hmma(acc[1][nt], ah, bl);
            hmma(acc[2][nt], al, bh);
        }
    }
    {
        int r0 = I * 128 + w * 16 + (lane >> 2);
        int cb = (lane & 3) * 2;
        #pragma unroll
        for (int nt = 0; nt < 3; ++nt) {
            float s0 = acc[0][nt][0] + acc[1][nt][0] + acc[2][nt][0];
            float s1 = acc[0][nt][1] + acc[1][nt][1] + acc[2][nt][1];
            float s2 = acc[0][nt][2] + acc[1][nt][2] + acc[2][nt][2];
            float s3 = acc[0][nt][3] + acc[1][nt][3] + acc[2][nt][3];
            atomicAdd(&g_app[(size_t)r0 * NB + nt * 8 + cb],           s0);
            atomicAdd(&g_app[(size_t)r0 * NB + nt * 8 + cb + 1],       s1);
            atomicAdd(&g_app[(size_t)(r0 + 8) * NB + nt * 8 + cb],     s2);
            atomicAdd(&g_app[(size_t)(r0 + 8) * NB + nt * 8 + cb + 1], s3);
        }
    }

    if (I == J) return;

    // ---- transposed product: out_J rows w*16.., k over I-block ----
    #pragma unroll
    for (int tm = 0; tm < 3; tm++)
        #pragma unroll
        for (int nt = 0; nt < 3; nt++)
            #pragma unroll
            for (int q = 0; q < 4; q++) acc[tm][nt][q] = 0.0f;

    #pragma unroll
    for (int ks = 0; ks < 8; ++ks) {
        uint32_t ah[4], al[4];
        ldsm4t(ah[0], ah[1], ah[2], ah[3], sb + AHI2 + t_off + ks * 16 * ROWB);
        ldsm4t(al[0], al[1], al[2], al[3], sb + ALO2 + t_off + ks * 16 * ROWB);
        #pragma unroll
        for (int nt = 0; nt < 3; ++nt) {
            uint32_t bh[2], bl[2];
            ldsm2(bh[0], bh[1], sb + PIHI + nt * 8 * ROWB + b_off + ks * 32);
            ldsm2(bl[0], bl[1], sb + PILO + nt * 8 * ROWB + b_off + ks * 32);
            hmma(acc[0][nt], ah, bh);
            hmma(acc[1][nt], ah, bl);
            hmma(acc[2][nt], al, bh);
        }
    }
    {
        int r0 = J * 128 + w * 16 + (lane >> 2);
        int cb = (lane & 3) * 2;
        #pragma unroll
        for (int nt = 0; nt < 3; ++nt) {
            float s0 = acc[0][nt][0] + acc[1][nt][0] + acc[2][nt][0];
            float s1 = acc[0][nt][1] + acc[1][nt][1] + acc[2][nt][1];
            float s2 = acc[0][nt][2] + acc[1][nt][2] + acc[2][nt][2];
            float s3 = acc[0][nt][3] + acc[1][nt][3] + acc[2][nt][3];
            atomicAdd(&g_app[(size_t)r0 * NB + nt * 8 + cb],           s0);
            atomicAdd(&g_app[(size_t)r0 * NB + nt * 8 + cb + 1],       s1);
            atomicAdd(&g_app[(size_t)(r0 + 8) * NB + nt * 8 + cb],     s2);
            atomicAdd(&g_app[(size_t)(r0 + 8) * NB + nt * 8 + cb + 1], s3);
        }
    }
}

// Separable smoothness: horizontal pass.
__global__ void k_convx(const float* __restrict__ out_cm) {
    __shared__ float sg[HH];
    if (threadIdx.x < HH) sg[threadIdx.x] = g_gauss[threadIdx.x];
    __syncthreads();
    int idx = blockIdx.x * blockDim.x + threadIdx.x;
    if (idx >= CC * NPIX) return;
    int xp = idx % HH;
    const float* row = out_cm + (idx - xp);
    float s = 0.0f;
    #pragma unroll 8
    for (int xx = 0; xx < HH; ++xx) {
        int d = xx - xp; d = (d < 0) ? -d : d;
        s += row[xx] * sg[d];
    }
    g_tmp[idx] = s;
}

// Separable smoothness: vertical pass.
__global__ void k_convy() {
    __shared__ float sg[HH];
    if (threadIdx.x < HH) sg[threadIdx.x] = g_gauss[threadIdx.x];
    __syncthreads();
    int idx = blockIdx.x * blockDim.x + threadIdx.x;
    if (idx >= CC * NPIX) return;
    int xp = idx % HH;
    int yp = (idx / HH) % HH;
    int c  = idx / NPIX;
    const float* col = g_tmp + c * NPIX + xp;
    float s = 0.0f;
    #pragma unroll 8
    for (int y = 0; y < HH; ++y) {
        int d = y - yp; d = (d < 0) ? -d : d;
        s += col[y * HH] * sg[d];
    }
    g_smo[idx] = s;
}

__global__ void k_combine(const float* __restrict__ mu, float* __restrict__ out_cm) {
    __shared__ float smu[CC * CC];
    for (int i = threadIdx.x; i < CC * CC; i += blockDim.x) smu[i] = mu[i];
    __syncthreads();
    int n = blockIdx.x * blockDim.x + threadIdx.x;
    if (n >= NPIX) return;
    float m[CC];
    #pragma unroll
    for (int c = 0; c < CC; c++)
        m[c] = g_app[(size_t)n * NB + c] + SMO_W * g_smo[c * NPIX + n];
    float u[CC];
    float mx = -1e30f;
    #pragma unroll
    for (int c = 0; c < CC; c++) {
        float s = 0.0f;
        #pragma unroll
        for (int c2 = 0; c2 < CC; c2++) s = fmaf(smu[c2 * CC + c], m[c2], s);
        float v = g_unary[c * NPIX + n] + s;
        g_unary[c * NPIX + n] = v;
        u[c] = v;
        mx = fmaxf(mx, v);
    }
    float s = 0.0f;
    #pragma unroll
    for (int c = 0; c < CC; c++) { u[c] = __expf(u[c] - mx); s += u[c]; }
    write_probs(n, u, 1.0f / s, out_cm);
}

// ---------------- launch ----------------
extern "C" void kernel_launch(void* const* d_in, const int* in_sizes, int n_in,
                              void* d_out, int out_size) {
    const float* x    = (const float*)d_in[0];
    const float* yhat = (const float*)d_in[1];
    const float* mu   = (const float*)d_in[2];
    float* out = (float*)d_out;

    cudaFuncSetAttribute(k_gemm_sym, cudaFuncAttributeMaxDynamicSharedMemorySize, GEMM_SMEM);

    k_feat<<<(NPIX + 255) / 256, 256>>>(x);
    k_build_sym<<<BTB * (BTB + 1) / 2, 256>>>();
    k_init<<<(NPIX + 255) / 256, 256>>>(yhat, out);

    for (int it = 0; it < CRF_ITERS; ++it) {
        k_zero<<<(NPIX * NB + 255) / 256, 256>>>();
        k_gemm_sym<<<NPAIR, 256, GEMM_SMEM>>>();
        k_convx<<<(CC * NPIX + 127) / 128, 128>>>(out);
        k_convy<<<(CC * NPIX + 127) / 128, 128>>>();
        k_combine<<<(NPIX + 127) / 128, 128>>>(mu, out);
    }
}